// round 1
// baseline (speedup 1.0000x reference)
#include <cuda_runtime.h>
#include <math.h>

#define D    64
#define G5   320          // 5*D
#define CPB  8            // cells per block
#define NTH  320          // threads per block (one per gate column)

// Scratch ping-pong buffers (allocation-free: __device__ globals).
// Level 0 output: 2^18 rows; odd levels at most 2^17 rows.
__device__ float g_A_h[(1 << 18) * D];
__device__ float g_A_c[(1 << 18) * D];
__device__ float g_B_h[(1 << 17) * D];
__device__ float g_B_c[(1 << 17) * D];
// Per-level Fenwick representatives (last row of each level's INPUT), 19 levels.
__device__ float g_lvl_h[19 * D];
__device__ float g_lvl_c[19 * D];

__device__ __forceinline__ float sigf(float x) {
    return 1.0f / (1.0f + expf(-x));
}

// One block handles CPB cells. Thread tid computes gate column tid for all CPB cells.
__global__ __launch_bounds__(NTH)
void merge_kernel(const float* __restrict__ hb, const float* __restrict__ cb,
                  int src_sel, int dst_sel,
                  const float* __restrict__ Wl, const float* __restrict__ Wr,
                  const float* __restrict__ b,
                  int n_out, int level)
{
    const float* h_src = (src_sel == 0) ? hb : (src_sel == 1 ? g_A_h : g_B_h);
    const float* c_src = (src_sel == 0) ? cb : (src_sel == 1 ? g_A_c : g_B_c);
    float* h_dst = (dst_sel == 1) ? g_A_h : g_B_h;
    float* c_dst = (dst_sel == 1) ? g_A_c : g_B_c;

    __shared__ __align__(16) float s_h[CPB][2 * D];  // [0..63]=hl, [64..127]=hr
    __shared__ float s_g[CPB][G5];

    const int tid   = threadIdx.x;
    const int cell0 = blockIdx.x * CPB;

    // Stage hl|hr for the CPB cells (rows 2c and 2c+1 are contiguous in src).
    for (int idx = tid; idx < CPB * 2 * D; idx += NTH) {
        int c   = idx >> 7;
        int off = idx & 127;
        int cell = cell0 + c;
        s_h[c][off] = (cell < n_out) ? h_src[cell * (2 * D) + off] : 0.0f;
    }
    __syncthreads();

    // g = hl @ Wl + hr @ Wr + b  for all CPB cells, column tid.
    float acc[CPB];
    {
        const float bb = b[tid];
#pragma unroll
        for (int c = 0; c < CPB; ++c) acc[c] = bb;
    }
    const float* wlp = Wl + tid;
    const float* wrp = Wr + tid;
#pragma unroll 4
    for (int k4 = 0; k4 < D / 4; ++k4) {
        float wl0 = wlp[(4 * k4 + 0) * G5];
        float wl1 = wlp[(4 * k4 + 1) * G5];
        float wl2 = wlp[(4 * k4 + 2) * G5];
        float wl3 = wlp[(4 * k4 + 3) * G5];
        float wr0 = wrp[(4 * k4 + 0) * G5];
        float wr1 = wrp[(4 * k4 + 1) * G5];
        float wr2 = wrp[(4 * k4 + 2) * G5];
        float wr3 = wrp[(4 * k4 + 3) * G5];
#pragma unroll
        for (int c = 0; c < CPB; ++c) {
            float4 hl = *reinterpret_cast<const float4*>(&s_h[c][4 * k4]);
            float4 hr = *reinterpret_cast<const float4*>(&s_h[c][D + 4 * k4]);
            float a = acc[c];
            a = fmaf(wl0, hl.x, a); a = fmaf(wr0, hr.x, a);
            a = fmaf(wl1, hl.y, a); a = fmaf(wr1, hr.y, a);
            a = fmaf(wl2, hl.z, a); a = fmaf(wr2, hr.z, a);
            a = fmaf(wl3, hl.w, a); a = fmaf(wr3, hr.w, a);
            acc[c] = a;
        }
    }
#pragma unroll
    for (int c = 0; c < CPB; ++c) s_g[c][tid] = acc[c];
    __syncthreads();

    // Elementwise LSTM cell update. Gate order: i, o, u, fl, fr.
    for (int idx = tid; idx < CPB * D; idx += NTH) {
        int c = idx >> 6;
        int d = idx & 63;
        int cell = cell0 + c;
        if (cell < n_out) {
            float gi  = s_g[c][0 * D + d];
            float go  = s_g[c][1 * D + d];
            float gu  = s_g[c][2 * D + d];
            float gfl = s_g[c][3 * D + d];
            float gfr = s_g[c][4 * D + d];
            float cl = c_src[(2 * cell)     * D + d];
            float cr = c_src[(2 * cell + 1) * D + d];
            float cc = sigf(gi) * tanhf(gu) + sigf(gfl) * cl + sigf(gfr) * cr;
            float hh = sigf(go) * tanhf(cc);
            c_dst[cell * D + d] = cc;
            h_dst[cell * D + d] = hh;
        }
    }

    // Fenwick representative: last row of this level's INPUT.
    if (blockIdx.x == 0 && tid < D) {
        int last = 2 * n_out - 1;
        g_lvl_h[level * D + tid] = h_src[last * D + tid];
        g_lvl_c[level * D + tid] = c_src[last * D + tid];
    }
}

// Sequential summary fold over per-level representatives. Root state is in A
// (level 18 writes buffer A). Single block, 320 threads.
__global__ __launch_bounds__(NTH)
void summary_kernel(const float* __restrict__ Wl, const float* __restrict__ Wr,
                    const float* __restrict__ b, int n_lvls, float* __restrict__ out)
{
    __shared__ float sh[D], sc[D], g[G5];
    const int tid = threadIdx.x;
    if (tid < D) {
        sh[tid] = g_A_h[tid];
        sc[tid] = g_A_c[tid];
    }
    __syncthreads();

    for (int l = n_lvls - 1; l >= 0; --l) {
        const float* lh = g_lvl_h + l * D;
        const float* lc = g_lvl_c + l * D;
        float acc = b[tid];
#pragma unroll 8
        for (int k = 0; k < D; ++k) {
            acc = fmaf(sh[k], Wl[k * G5 + tid], acc);
            acc = fmaf(lh[k], Wr[k * G5 + tid], acc);
        }
        g[tid] = acc;
        __syncthreads();
        if (tid < D) {
            float gi  = g[0 * D + tid];
            float go  = g[1 * D + tid];
            float gu  = g[2 * D + tid];
            float gfl = g[3 * D + tid];
            float gfr = g[4 * D + tid];
            float cc = sigf(gi) * tanhf(gu) + sigf(gfl) * sc[tid] + sigf(gfr) * lc[tid];
            float hh = sigf(go) * tanhf(cc);
            sc[tid] = cc;
            sh[tid] = hh;
        }
        __syncthreads();
    }
    if (tid < D) {
        out[tid]     = sh[tid];   // sh row
        out[D + tid] = sc[tid];   // sc row
    }
}

extern "C" void kernel_launch(void* const* d_in, const int* in_sizes, int n_in,
                              void* d_out, int out_size)
{
    const float* h_bot = (const float*)d_in[0];
    const float* c_bot = (const float*)d_in[1];
    const float* mWl   = (const float*)d_in[2];
    const float* mWr   = (const float*)d_in[3];
    const float* mb    = (const float*)d_in[4];
    const float* sWl   = (const float*)d_in[5];
    const float* sWr   = (const float*)d_in[6];
    const float* sb    = (const float*)d_in[7];

    int n = in_sizes[0] / D;   // 524288 leaves
    int level = 0;
    int src_sel = 0;
    while (n > 1) {
        int n_out = n >> 1;
        int dst_sel = (level & 1) ? 2 : 1;
        int blocks = (n_out + CPB - 1) / CPB;
        merge_kernel<<<blocks, NTH>>>(h_bot, c_bot, src_sel, dst_sel,
                                      mWl, mWr, mb, n_out, level);
        src_sel = dst_sel;
        n = n_out;
        ++level;
    }
    summary_kernel<<<1, NTH>>>(sWl, sWr, sb, level, (float*)d_out);
}

// round 2
// speedup vs baseline: 1.4840x; 1.4840x over previous
#include <cuda_runtime.h>
#include <math.h>

#define D    64
#define G5   320          // 5*D
#define NTH  320          // threads per block
#define NCT  80           // column-threads (80 * TC = 320 cols)
#define TC   4            // contiguous gate columns per thread
#define NCG  4            // cell groups per block
#define CG   8            // cells per group
#define CPB  32           // cells per block (NCG * CG)

// Scratch ping-pong buffers (allocation-free: __device__ globals).
__device__ float g_A_h[(1 << 18) * D];
__device__ float g_A_c[(1 << 18) * D];
__device__ float g_B_h[(1 << 17) * D];
__device__ float g_B_c[(1 << 17) * D];
// Per-level Fenwick representatives (last row of each level's INPUT), 19 levels.
__device__ float g_lvl_h[19 * D];
__device__ float g_lvl_c[19 * D];

__device__ __forceinline__ float sigf(float x) {
    return 1.0f / (1.0f + expf(-x));
}

// One block: 32 cells x 320 gate columns. Thread (cg, ct) computes columns
// [4*ct, 4*ct+4) for cells [cell0 + 8*cg, cell0 + 8*cg + 8).
__global__ __launch_bounds__(NTH, 2)
void merge_kernel(const float* __restrict__ hb, const float* __restrict__ cb,
                  int src_sel, int dst_sel,
                  const float* __restrict__ Wl, const float* __restrict__ Wr,
                  const float* __restrict__ b,
                  int n_out, int level)
{
    const float* h_src = (src_sel == 0) ? hb : (src_sel == 1 ? g_A_h : g_B_h);
    const float* c_src = (src_sel == 0) ? cb : (src_sel == 1 ? g_A_c : g_B_c);
    float* h_dst = (dst_sel == 1) ? g_A_h : g_B_h;
    float* c_dst = (dst_sel == 1) ? g_A_c : g_B_c;

    // 40 KB buffer. Phase 1: first 16 KB = interleaved h-stage.
    // Phase 2 (after h is dead): full 40 KB = gate matrix [CPB][G5].
    __shared__ __align__(16) float s_buf[CPB * G5];

    const int tid   = threadIdx.x;
    const int cell0 = blockIdx.x * CPB;
    const int ct    = tid % NCT;
    const int cg    = tid / NCT;

    // ---- Stage h interleaved: s_h2[c][4*(k>>1) + 2*(k&1) + lr] ----
    // A float4 at s_h2[c] + 4*k2 holds {hl[2k2], hr[2k2], hl[2k2+1], hr[2k2+1]}.
    float* s_h2 = s_buf;
    {
        const float4* src4 = reinterpret_cast<const float4*>(h_src) + (size_t)cell0 * 32;
        for (int idx = tid; idx < CPB * 2 * 16; idx += NTH) {
            int r  = idx >> 4;      // row within block's 64 input rows
            int f4 = idx & 15;
            int c  = r >> 1;
            int lr = r & 1;
            float4 v = make_float4(0.f, 0.f, 0.f, 0.f);
            if (cell0 + c < n_out) v = src4[idx];
            float* dst = s_h2 + c * 128 + 8 * f4 + lr;
            dst[0] = v.x; dst[2] = v.y; dst[4] = v.z; dst[6] = v.w;
        }
    }
    __syncthreads();

    // ---- GEMM phase: acc[c][j] = b + sum_k hl*Wl + hr*Wr ----
    const float4* wl4 = reinterpret_cast<const float4*>(Wl);  // [k*80 + col4]
    const float4* wr4 = reinterpret_cast<const float4*>(Wr);
    float4 b4 = reinterpret_cast<const float4*>(b)[ct];

    float acc[CG][TC];
#pragma unroll
    for (int c = 0; c < CG; ++c) {
        acc[c][0] = b4.x; acc[c][1] = b4.y; acc[c][2] = b4.z; acc[c][3] = b4.w;
    }

    const float4* hbase = reinterpret_cast<const float4*>(s_h2) + (cg * CG) * 32;

#pragma unroll 2
    for (int k2 = 0; k2 < 32; ++k2) {
        float4 wl0 = wl4[(2 * k2    ) * NCT + ct];
        float4 wr0 = wr4[(2 * k2    ) * NCT + ct];
        float4 wl1 = wl4[(2 * k2 + 1) * NCT + ct];
        float4 wr1 = wr4[(2 * k2 + 1) * NCT + ct];
#pragma unroll
        for (int c = 0; c < CG; ++c) {
            float4 hv = hbase[c * 32 + k2];   // {hl[2k2], hr[2k2], hl[2k2+1], hr[2k2+1]}
            float a0 = acc[c][0], a1 = acc[c][1], a2 = acc[c][2], a3 = acc[c][3];
            a0 = fmaf(wl0.x, hv.x, a0); a1 = fmaf(wl0.y, hv.x, a1);
            a2 = fmaf(wl0.z, hv.x, a2); a3 = fmaf(wl0.w, hv.x, a3);
            a0 = fmaf(wr0.x, hv.y, a0); a1 = fmaf(wr0.y, hv.y, a1);
            a2 = fmaf(wr0.z, hv.y, a2); a3 = fmaf(wr0.w, hv.y, a3);
            a0 = fmaf(wl1.x, hv.z, a0); a1 = fmaf(wl1.y, hv.z, a1);
            a2 = fmaf(wl1.z, hv.z, a2); a3 = fmaf(wl1.w, hv.z, a3);
            a0 = fmaf(wr1.x, hv.w, a0); a1 = fmaf(wr1.y, hv.w, a1);
            a2 = fmaf(wr1.z, hv.w, a2); a3 = fmaf(wr1.w, hv.w, a3);
            acc[c][0] = a0; acc[c][1] = a1; acc[c][2] = a2; acc[c][3] = a3;
        }
    }
    __syncthreads();   // everyone done reading s_h2; buffer is reusable

    // ---- Exchange gates through smem ----
#pragma unroll
    for (int c = 0; c < CG; ++c) {
        float4* p = reinterpret_cast<float4*>(s_buf + (cg * CG + c) * G5) + ct;
        *p = make_float4(acc[c][0], acc[c][1], acc[c][2], acc[c][3]);
    }
    __syncthreads();

    // ---- Elementwise LSTM update. Gate order: i, o, u, fl, fr. ----
    for (int idx = tid; idx < CPB * D; idx += NTH) {
        int c = idx >> 6;
        int d = idx & 63;
        int cell = cell0 + c;
        if (cell < n_out) {
            const float* g = s_buf + c * G5;
            float gi  = g[0 * D + d];
            float go  = g[1 * D + d];
            float gu  = g[2 * D + d];
            float gfl = g[3 * D + d];
            float gfr = g[4 * D + d];
            float cl = c_src[(size_t)(2 * cell)     * D + d];
            float cr = c_src[(size_t)(2 * cell + 1) * D + d];
            float cc = sigf(gi) * tanhf(gu) + sigf(gfl) * cl + sigf(gfr) * cr;
            float hh = sigf(go) * tanhf(cc);
            c_dst[(size_t)cell * D + d] = cc;
            h_dst[(size_t)cell * D + d] = hh;
        }
    }

    // Fenwick representative: last row of this level's INPUT.
    if (blockIdx.x == 0 && tid < D) {
        int last = 2 * n_out - 1;
        g_lvl_h[level * D + tid] = h_src[(size_t)last * D + tid];
        g_lvl_c[level * D + tid] = c_src[(size_t)last * D + tid];
    }
}

// Sequential summary fold over per-level representatives. Root state in A.
__global__ __launch_bounds__(NTH)
void summary_kernel(const float* __restrict__ Wl, const float* __restrict__ Wr,
                    const float* __restrict__ b, int n_lvls, float* __restrict__ out)
{
    __shared__ float sh[D], sc[D], g[G5];
    const int tid = threadIdx.x;
    if (tid < D) {
        sh[tid] = g_A_h[tid];
        sc[tid] = g_A_c[tid];
    }
    __syncthreads();

    for (int l = n_lvls - 1; l >= 0; --l) {
        const float* lh = g_lvl_h + l * D;
        const float* lc = g_lvl_c + l * D;
        float acc = b[tid];
#pragma unroll 8
        for (int k = 0; k < D; ++k) {
            acc = fmaf(sh[k], Wl[k * G5 + tid], acc);
            acc = fmaf(lh[k], Wr[k * G5 + tid], acc);
        }
        g[tid] = acc;
        __syncthreads();
        if (tid < D) {
            float gi  = g[0 * D + tid];
            float go  = g[1 * D + tid];
            float gu  = g[2 * D + tid];
            float gfl = g[3 * D + tid];
            float gfr = g[4 * D + tid];
            float cc = sigf(gi) * tanhf(gu) + sigf(gfl) * sc[tid] + sigf(gfr) * lc[tid];
            float hh = sigf(go) * tanhf(cc);
            sc[tid] = cc;
            sh[tid] = hh;
        }
        __syncthreads();
    }
    if (tid < D) {
        out[tid]     = sh[tid];
        out[D + tid] = sc[tid];
    }
}

extern "C" void kernel_launch(void* const* d_in, const int* in_sizes, int n_in,
                              void* d_out, int out_size)
{
    const float* h_bot = (const float*)d_in[0];
    const float* c_bot = (const float*)d_in[1];
    const float* mWl   = (const float*)d_in[2];
    const float* mWr   = (const float*)d_in[3];
    const float* mb    = (const float*)d_in[4];
    const float* sWl   = (const float*)d_in[5];
    const float* sWr   = (const float*)d_in[6];
    const float* sb    = (const float*)d_in[7];

    int n = in_sizes[0] / D;   // 524288 leaves
    int level = 0;
    int src_sel = 0;
    while (n > 1) {
        int n_out = n >> 1;
        int dst_sel = (level & 1) ? 2 : 1;
        int blocks = (n_out + CPB - 1) / CPB;
        merge_kernel<<<blocks, NTH>>>(h_bot, c_bot, src_sel, dst_sel,
                                      mWl, mWr, mb, n_out, level);
        src_sel = dst_sel;
        n = n_out;
        ++level;
    }
    summary_kernel<<<1, NTH>>>(sWl, sWr, sb, level, (float*)d_out);
}